// round 2
// baseline (speedup 1.0000x reference)
#include <cuda_runtime.h>
#include <cstdint>

// MergedEmbeddingBag: T=26 tables, R=100000 rows, D=128, B=4096, L=20.
// W: [T, R, D] fp32.  indices: [T, B, L] int32 (JAX downcasts int64 without x64).
// out: [T, B, D] fp32.  MODES alternate SUM/MEAN (odd table -> mean, /L).

constexpr int T = 26;
constexpr int R = 100000;
constexpr int D = 128;
constexpr int B = 4096;
constexpr int L = 20;
constexpr int BAGS = T * B;           // 106496 bags, one warp each
constexpr int D4 = D / 4;             // 32 float4 per row -> 1 per lane

__global__ __launch_bounds__(256, 8)
void merged_embedding_bag_kernel(const float4* __restrict__ W4,
                                 const int* __restrict__ indices,
                                 float4* __restrict__ out4)
{
    const int gwarp = (blockIdx.x * blockDim.x + threadIdx.x) >> 5;
    const int lane  = threadIdx.x & 31;
    if (gwarp >= BAGS) return;

    const int t = gwarp / B;                 // table id
    const int* __restrict__ ip = indices + (size_t)gwarp * L;

    // Base of this table's weights in float4 units.
    const float4* __restrict__ wt = W4 + (size_t)t * (size_t)R * D4;

    // Prefetch all 20 indices (same address across the warp -> broadcast txn).
    int ridx[L];
#pragma unroll
    for (int l = 0; l < L; l++) {
        int v = ip[l];
        // Defensive clamp: no-op for in-range indices; prevents OOB if the
        // dtype assumption is ever wrong (gives rel_err signal, not a crash).
        v = v < 0 ? 0 : (v >= R ? R - 1 : v);
        ridx[l] = v;
    }

    float ax = 0.f, ay = 0.f, az = 0.f, aw = 0.f;

    // Fully unrolled gather: ptxas front-batches the LDG.128s -> high MLP
    // to hide ~577-cycle DRAM latency.
#pragma unroll
    for (int l = 0; l < L; l++) {
        const float4 v = __ldg(&wt[(size_t)ridx[l] * D4 + lane]);
        ax += v.x; ay += v.y; az += v.z; aw += v.w;
    }

    // MEAN pooling on odd tables.
    const float s = (t & 1) ? (1.0f / (float)L) : 1.0f;
    float4 o;
    o.x = ax * s; o.y = ay * s; o.z = az * s; o.w = aw * s;

    out4[(size_t)gwarp * D4 + lane] = o;
}

extern "C" void kernel_launch(void* const* d_in, const int* in_sizes, int n_in,
                              void* d_out, int out_size)
{
    const float4* W4 = (const float4*)d_in[0];
    const int* indices = (const int*)d_in[1];
    float4* out4 = (float4*)d_out;

    const int threads = 256;                      // 8 warps / block
    const int warps_per_block = threads / 32;
    const int blocks = (BAGS + warps_per_block - 1) / warps_per_block;  // 13312

    merged_embedding_bag_kernel<<<blocks, threads>>>(W4, indices, out4);
}

// round 3
// speedup vs baseline: 1.0196x; 1.0196x over previous
#include <cuda_runtime.h>
#include <cstdint>

// MergedEmbeddingBag: T=26 tables, R=100000 rows, D=128, B=4096, L=20.
// W: [T, R, D] fp32.  indices: [T, B, L] int32.  out: [T, B, D] fp32.
// Odd tables -> MEAN (divide by L), even -> SUM.
//
// One warp per bag; lane owns one float4 (512B/row = 4x128B lines, fully
// coalesced). Gather is split into two front-batched groups of 10 LDG.128
// each to maximize MLP (reg budget ~64 via launch_bounds(256,4)).
// Output uses streaming stores to keep table rows resident in L2.

constexpr int T = 26;
constexpr int R = 100000;
constexpr int D = 128;
constexpr int B = 4096;
constexpr int L = 20;
constexpr int BAGS = T * B;           // 106496 bags
constexpr int D4 = D / 4;             // 32 float4 per row -> 1 per lane
constexpr int HALF = L / 2;           // 10

__global__ __launch_bounds__(256, 4)
void merged_embedding_bag_kernel(const float4* __restrict__ W4,
                                 const int* __restrict__ indices,
                                 float4* __restrict__ out4)
{
    const int gwarp = (blockIdx.x * blockDim.x + threadIdx.x) >> 5;
    const int lane  = threadIdx.x & 31;
    if (gwarp >= BAGS) return;

    const int t = gwarp / B;                 // table id
    const int* __restrict__ ip = indices + (size_t)gwarp * L;

    const float4* __restrict__ wt = W4 + (size_t)t * (size_t)R * D4;

    // Load all 20 indices up front (warp-broadcast txns).
    int ridx[L];
#pragma unroll
    for (int l = 0; l < L; l++) {
        int v = ip[l];
        v = v < 0 ? 0 : (v >= R ? R - 1 : v);   // defensive, free vs DRAM lat
        ridx[l] = v;
    }

    float ax = 0.f, ay = 0.f, az = 0.f, aw = 0.f;

    // ---- batch 1: 10 loads in flight, then accumulate ----
    {
        float4 v[HALF];
#pragma unroll
        for (int l = 0; l < HALF; l++)
            v[l] = __ldg(&wt[(size_t)ridx[l] * D4 + lane]);
#pragma unroll
        for (int l = 0; l < HALF; l++) {
            ax += v[l].x; ay += v[l].y; az += v[l].z; aw += v[l].w;
        }
    }
    // ---- batch 2 ----
    {
        float4 v[HALF];
#pragma unroll
        for (int l = 0; l < HALF; l++)
            v[l] = __ldg(&wt[(size_t)ridx[HALF + l] * D4 + lane]);
#pragma unroll
        for (int l = 0; l < HALF; l++) {
            ax += v[l].x; ay += v[l].y; az += v[l].z; aw += v[l].w;
        }
    }

    const float s = (t & 1) ? (1.0f / (float)L) : 1.0f;
    float4 o;
    o.x = ax * s; o.y = ay * s; o.z = az * s; o.w = aw * s;

    // Streaming store: evict-first, don't pollute L2's table working set.
    __stcs(&out4[(size_t)gwarp * D4 + lane], o);
}

extern "C" void kernel_launch(void* const* d_in, const int* in_sizes, int n_in,
                              void* d_out, int out_size)
{
    const float4* W4 = (const float4*)d_in[0];
    const int* indices = (const int*)d_in[1];
    float4* out4 = (float4*)d_out;

    const int threads = 256;                      // 8 warps / block
    const int warps_per_block = threads / 32;
    const int blocks = (BAGS + warps_per_block - 1) / warps_per_block;  // 13312

    merged_embedding_bag_kernel<<<blocks, threads>>>(W4, indices, out4);
}